// round 10
// baseline (speedup 1.0000x reference)
#include <cuda_runtime.h>

#define NN 384
#define DD 128
#define MARGIN_F 0.2f
#define APB 4
#define NBLK (NN / APB)     // 96 blocks -> single wave
#define TK 16               // k-slice per tile
#define TPAD 385            // smem tile j-stride (conflict-free col reads)
#define MAXPOS 64
#define NWARP 12

// Scratch (no allocations allowed)
__device__ float g_total;
__device__ float g_count;
__device__ unsigned int g_ctr;

__global__ void __launch_bounds__(NN) fused_k(
    const float* __restrict__ feat,
    const int*   __restrict__ y,
    float*       __restrict__ out)
{
    const int t = threadIdx.x;        // column j
    const int ab = blockIdx.x * APB;
    const int w = t >> 5, lane = t & 31;
    const unsigned FULL = 0xFFFFFFFFu;

    __shared__ float T[TK * TPAD];    // [k][j] feat slice, transposed
    __shared__ float fa[APB][DD];     // anchor rows
    __shared__ float ras[APB];
    __shared__ int   yas[APB];
    __shared__ float pos_d[APB][MAXPOS];
    __shared__ int   wc[APB][NWARP];
    __shared__ int   wbase[APB][NWARP];
    __shared__ int   np_s[APB];
    __shared__ float red_f[NWARP];

    // stage anchor rows (4 x 128 = 512 floats; 128 float4 loads)
    if (t < APB * (DD / 4)) {
        const int m = t >> 5;         // t / 32
        const int k4 = t & 31;
        const float4 v = reinterpret_cast<const float4*>(feat + (ab + m) * DD)[k4];
        fa[m][4 * k4 + 0] = v.x; fa[m][4 * k4 + 1] = v.y;
        fa[m][4 * k4 + 2] = v.z; fa[m][4 * k4 + 3] = v.w;
    }
    if (t < APB) yas[t] = y[ab + t];
    const int yj = __ldg(&y[t]);

    // ---- dot phase: 8 k-tiles of [TK][NN] ----
    float dot0 = 0.f, dot1 = 0.f, dot2 = 0.f, dot3 = 0.f, rr = 0.f;

    const int lrow = t >> 2;          // 0..95 (row within pass)
    const int lk4  = t & 3;           // float4 index within TK window

#pragma unroll 1
    for (int kc = 0; kc < DD; kc += TK) {
        __syncthreads();              // previous tile fully consumed
        // load 384 rows x TK cols: 4 passes of 96 rows
#pragma unroll
        for (int r = 0; r < 4; r++) {
            const int row = r * 96 + lrow;
            const float4 v = *reinterpret_cast<const float4*>(
                feat + row * DD + kc + 4 * lk4);
            T[(4 * lk4 + 0) * TPAD + row] = v.x;
            T[(4 * lk4 + 1) * TPAD + row] = v.y;
            T[(4 * lk4 + 2) * TPAD + row] = v.z;
            T[(4 * lk4 + 3) * TPAD + row] = v.w;
        }
        __syncthreads();
        // compute: thread t reads column t of the tile
#pragma unroll
        for (int k = 0; k < TK; k++) {
            const float v = T[k * TPAD + t];
            dot0 += fa[0][kc + k] * v;
            dot1 += fa[1][kc + k] * v;
            dot2 += fa[2][kc + k] * v;
            dot3 += fa[3][kc + k] * v;
            rr   += v * v;
        }
    }

    // publish anchor norms (thread t == anchor index holds its own rr)
    if (t == ab + 0) ras[0] = rr;
    if (t == ab + 1) ras[1] = rr;
    if (t == ab + 2) ras[2] = rr;
    if (t == ab + 3) ras[3] = rr;
    __syncthreads();

    // ---- d2 + ballot compaction ----
    float d2[APB];
    bool  isp[APB];
    unsigned pm[APB];
    const float dts[APB] = {dot0, dot1, dot2, dot3};
#pragma unroll
    for (int m = 0; m < APB; m++) {
        d2[m] = fmaxf(ras[m] + rr - 2.0f * dts[m], 0.0f);
        isp[m] = (yj == yas[m]) && (t != ab + m);
        pm[m] = __ballot_sync(FULL, isp[m]);
        if (lane == 0) wc[m][w] = __popc(pm[m]);
    }
    __syncthreads();
    if (t < APB) {
        int s = 0;
#pragma unroll
        for (int ww = 0; ww < NWARP; ww++) { wbase[t][ww] = s; s += wc[t][ww]; }
        np_s[t] = s;
    }
    __syncthreads();
#pragma unroll
    for (int m = 0; m < APB; m++) {
        if (isp[m]) {
            const int idx = wbase[m][w] + __popc(pm[m] & ((1u << lane) - 1u));
            pos_d[m][idx] = d2[m] + MARGIN_F;
        }
    }
    __syncthreads();

    // ---- triplet sums: thread t is candidate negative ----
    float acc = 0.0f;
#pragma unroll
    for (int m = 0; m < APB; m++) {
        const int npm = np_s[m];
        if (yj != yas[m]) {
            const float dn = d2[m];
            for (int i = 0; i < npm; i++) {
                const float v = pos_d[m][i] - dn;
                acc += (v > 0.0f) ? v : 0.0f;
            }
        }
    }

    // ---- reduce + global accumulate + last-block finalize ----
#pragma unroll
    for (int off = 16; off > 0; off >>= 1)
        acc += __shfl_down_sync(FULL, acc, off);
    if (lane == 0) red_f[w] = acc;
    __syncthreads();
    if (w == 0) {
        float af = (lane < NWARP) ? red_f[lane] : 0.0f;
#pragma unroll
        for (int off = 8; off > 0; off >>= 1)
            af += __shfl_down_sync(FULL, af, off);
        if (lane == 0) {
            int cnt = 0;
#pragma unroll
            for (int m = 0; m < APB; m++)
                cnt += np_s[m] * (NN - 1 - np_s[m]);
            atomicAdd(&g_total, af);
            atomicAdd(&g_count, (float)cnt);
            __threadfence();
            const unsigned done = atomicAdd(&g_ctr, 1u);
            if (done == NBLK - 1) {
                const float tot = atomicAdd(&g_total, 0.0f);
                const float cn  = atomicAdd(&g_count, 0.0f);
                out[0] = tot / cn;
                g_total = 0.0f;
                g_count = 0.0f;
                g_ctr   = 0u;
            }
        }
    }
}

extern "C" void kernel_launch(void* const* d_in, const int* in_sizes, int n_in,
                              void* d_out, int out_size) {
    const float* feat = (const float*)d_in[0];
    // d_in[1] = logits (unused by the loss)
    const int*   yv   = (const int*)d_in[2];
    float* out = (float*)d_out;

    fused_k<<<NBLK, NN>>>(feat, yv, out);
}

// round 11
// speedup vs baseline: 1.1800x; 1.1800x over previous
#include <cuda_runtime.h>

#define NN 384
#define DD 128
#define MARGIN_F 0.2f
#define APB 4
#define NBLK (NN / APB)     // 96 blocks -> single wave
#define TK 32               // k-slice per tile (4 tiles)
#define TPAD 33             // smem row stride (floats): conflict-free
#define MAXPOS 64
#define NWARP 12
#define TSMEM (NN * TPAD * 4)   // dynamic smem bytes

// Scratch (no allocations allowed)
__device__ float g_total;
__device__ float g_count;
__device__ unsigned int g_ctr;

__global__ void __launch_bounds__(NN) fused_k(
    const float* __restrict__ feat,
    const int*   __restrict__ y,
    float*       __restrict__ out)
{
    extern __shared__ float T[];      // [row][k] tile, 384 x 33
    const int t = threadIdx.x;        // column j == own row in tile
    const int ab = blockIdx.x * APB;
    const int w = t >> 5, lane = t & 31;
    const unsigned FULL = 0xFFFFFFFFu;

    __shared__ float4 fa4[APB][DD / 4];
    __shared__ float  ras[APB];
    __shared__ int    yas[APB];
    __shared__ float  pos_d[APB][MAXPOS];
    __shared__ int    wc[APB][NWARP];
    __shared__ int    wbase[APB][NWARP];
    __shared__ int    np_s[APB];
    __shared__ float  red_f[NWARP];

    // stage anchor rows: 128 threads x 1 float4 x 4 anchors
    if (t < 128) {
        const int m = t >> 5, k4 = t & 31;
        fa4[m][k4] = reinterpret_cast<const float4*>(feat + (ab + m) * DD)[k4];
    }
    if (t < APB) yas[t] = y[ab + t];
    const int yj = __ldg(&y[t]);

    // per-thread load slots: f = p*384 + t -> row f>>3, float4-col f&7
    const int r_[8] = {
        (0 * NN + t) >> 3, (1 * NN + t) >> 3, (2 * NN + t) >> 3, (3 * NN + t) >> 3,
        (4 * NN + t) >> 3, (5 * NN + t) >> 3, (6 * NN + t) >> 3, (7 * NN + t) >> 3};
    const int k4_ = t & 7;  // same for all p since NN % 8 == 0

    float4 pre[8];
#pragma unroll
    for (int p = 0; p < 8; p++)
        pre[p] = *reinterpret_cast<const float4*>(feat + r_[p] * DD + 4 * k4_);

    float dot0 = 0.f, dot1 = 0.f, dot2 = 0.f, dot3 = 0.f, rr = 0.f;

#pragma unroll
    for (int tile = 0; tile < DD / TK; tile++) {
        const int kc = tile * TK;
        // store current tile (scalar STS, conflict-free)
#pragma unroll
        for (int p = 0; p < 8; p++) {
            float* dst = &T[r_[p] * TPAD + 4 * k4_];
            dst[0] = pre[p].x; dst[1] = pre[p].y;
            dst[2] = pre[p].z; dst[3] = pre[p].w;
        }
        __syncthreads();
        // prefetch next tile while computing this one
        if (tile < DD / TK - 1) {
#pragma unroll
            for (int p = 0; p < 8; p++)
                pre[p] = *reinterpret_cast<const float4*>(
                    feat + r_[p] * DD + (kc + TK) + 4 * k4_);
        }
        // compute: thread t consumes its own row
        const float* Trow = &T[t * TPAD];
#pragma unroll
        for (int kk = 0; kk < TK / 4; kk++) {
            const float v0 = Trow[4 * kk + 0];
            const float v1 = Trow[4 * kk + 1];
            const float v2 = Trow[4 * kk + 2];
            const float v3 = Trow[4 * kk + 3];
            const int ki = kc / 4 + kk;
            float4 a;
            a = fa4[0][ki];
            dot0 += a.x * v0; dot0 += a.y * v1; dot0 += a.z * v2; dot0 += a.w * v3;
            a = fa4[1][ki];
            dot1 += a.x * v0; dot1 += a.y * v1; dot1 += a.z * v2; dot1 += a.w * v3;
            a = fa4[2][ki];
            dot2 += a.x * v0; dot2 += a.y * v1; dot2 += a.z * v2; dot2 += a.w * v3;
            a = fa4[3][ki];
            dot3 += a.x * v0; dot3 += a.y * v1; dot3 += a.z * v2; dot3 += a.w * v3;
            rr += v0 * v0; rr += v1 * v1; rr += v2 * v2; rr += v3 * v3;
        }
        __syncthreads();
    }

    // publish anchor norms (thread t == anchor index holds its own rr)
    if (t - ab >= 0 && t - ab < APB) ras[t - ab] = rr;
    __syncthreads();

    // ---- d2 + ballot compaction ----
    float d2[APB];
    bool  isp[APB];
    unsigned pm[APB];
    const float dts[APB] = {dot0, dot1, dot2, dot3};
#pragma unroll
    for (int m = 0; m < APB; m++) {
        d2[m] = fmaxf(ras[m] + rr - 2.0f * dts[m], 0.0f);
        isp[m] = (yj == yas[m]) && (t != ab + m);
        pm[m] = __ballot_sync(FULL, isp[m]);
        if (lane == 0) wc[m][w] = __popc(pm[m]);
    }
    __syncthreads();
    if (t < APB) {
        int s = 0;
#pragma unroll
        for (int ww = 0; ww < NWARP; ww++) { wbase[t][ww] = s; s += wc[t][ww]; }
        np_s[t] = s;
    }
    __syncthreads();
#pragma unroll
    for (int m = 0; m < APB; m++) {
        if (isp[m]) {
            const int idx = wbase[m][w] + __popc(pm[m] & ((1u << lane) - 1u));
            pos_d[m][idx] = d2[m] + MARGIN_F;
        }
    }
    __syncthreads();

    // ---- triplet sums: thread t is candidate negative ----
    float acc = 0.0f;
#pragma unroll
    for (int m = 0; m < APB; m++) {
        const int npm = np_s[m];
        if (yj != yas[m]) {
            const float dn = d2[m];
            for (int i = 0; i < npm; i++) {
                const float v = pos_d[m][i] - dn;
                acc += (v > 0.0f) ? v : 0.0f;
            }
        }
    }

    // ---- reduce + global accumulate + last-block finalize ----
#pragma unroll
    for (int off = 16; off > 0; off >>= 1)
        acc += __shfl_down_sync(FULL, acc, off);
    if (lane == 0) red_f[w] = acc;
    __syncthreads();
    if (w == 0) {
        float af = (lane < NWARP) ? red_f[lane] : 0.0f;
#pragma unroll
        for (int off = 8; off > 0; off >>= 1)
            af += __shfl_down_sync(FULL, af, off);
        if (lane == 0) {
            int cnt = 0;
#pragma unroll
            for (int m = 0; m < APB; m++)
                cnt += np_s[m] * (NN - 1 - np_s[m]);
            atomicAdd(&g_total, af);
            atomicAdd(&g_count, (float)cnt);
            __threadfence();
            const unsigned done = atomicAdd(&g_ctr, 1u);
            if (done == NBLK - 1) {
                const float tot = atomicAdd(&g_total, 0.0f);
                const float cn  = atomicAdd(&g_count, 0.0f);
                out[0] = tot / cn;
                g_total = 0.0f;
                g_count = 0.0f;
                g_ctr   = 0u;
            }
        }
    }
}

extern "C" void kernel_launch(void* const* d_in, const int* in_sizes, int n_in,
                              void* d_out, int out_size) {
    const float* feat = (const float*)d_in[0];
    // d_in[1] = logits (unused by the loss)
    const int*   yv   = (const int*)d_in[2];
    float* out = (float*)d_out;

    static int attr_set = 0;
    if (!attr_set) {
        cudaFuncSetAttribute(fused_k, cudaFuncAttributeMaxDynamicSharedMemorySize,
                             TSMEM);
        attr_set = 1;
    }
    fused_k<<<NBLK, NN, TSMEM>>>(feat, yv, out);
}